// round 7
// baseline (speedup 1.0000x reference)
#include <cuda_runtime.h>
#include <cuda_pipeline.h>
#include <mma.h>
#include <math.h>
#include <stddef.h>

using namespace nvcuda;

#define LQ    2048
#define BATCH 2
#define DIM   320
#define NH    8
#define HD    40
#define FF    1280
#define M_TOK (BATCH*LQ)   /* 4096 */

// -------------------- scratch (device globals) -----------------------------
__device__ float g_h  [M_TOK*DIM];
__device__ float g_q  [M_TOK*DIM];
__device__ float g_k  [M_TOK*DIM];
__device__ float g_v  [M_TOK*DIM];
__device__ float g_at [M_TOK*DIM];
__device__ float g_x1 [M_TOK*DIM];
__device__ float g_x2 [M_TOK*DIM];
__device__ float g_wc [DIM*DIM];
__device__ float g_mid[M_TOK*FF];

// -------------------- LayerNorm --------------------------------------------
__global__ void ln_kernel(const float* __restrict__ x, const float* __restrict__ g,
                          const float* __restrict__ b, float* __restrict__ out) {
    int row = blockIdx.x;
    int t   = threadIdx.x;           // 0..319
    float v = x[(size_t)row*DIM + t];
    float s = v, sq = v*v;
    #pragma unroll
    for (int o = 16; o > 0; o >>= 1) {
        s  += __shfl_xor_sync(0xffffffff, s,  o);
        sq += __shfl_xor_sync(0xffffffff, sq, o);
    }
    __shared__ float ws[10], wq[10];
    __shared__ float mean_s, rstd_s;
    int w = t >> 5;
    if ((t & 31) == 0) { ws[w] = s; wq[w] = sq; }
    __syncthreads();
    if (t == 0) {
        float S = 0.f, Q = 0.f;
        #pragma unroll
        for (int i = 0; i < 10; i++) { S += ws[i]; Q += wq[i]; }
        float m   = S * (1.0f/DIM);
        float var = Q * (1.0f/DIM) - m*m;
        mean_s = m;
        rstd_s = rsqrtf(var + 1e-5f);
    }
    __syncthreads();
    out[(size_t)row*DIM + t] = (v - mean_s) * rstd_s * g[t] + b[t];
}

// -------------------- small fp32 GEMM (only 320x320x320 for wc) ------------
__global__ void __launch_bounds__(256)
gemm_f32(const float* __restrict__ A, const float* __restrict__ B,
         float* __restrict__ C, int M, int N, int K) {
    __shared__ float As[32][64];
    __shared__ float Bs[32][64];
    const int tid = threadIdx.x;
    const int bx = blockIdx.x, by = blockIdx.y;
    const int ty = tid >> 4, tx = tid & 15;
    float acc[4][4] = {};
    const float* Ab = A + (size_t)by * 64 * K;
    const float* Bb = B + (size_t)bx * 64;
    for (int k0 = 0; k0 < K; k0 += 32) {
        #pragma unroll
        for (int l = 0; l < 2; l++) {
            int s  = tid + l*256;
            int ar = s >> 3, ac = (s & 7) << 2;
            float4 va = *(const float4*)(Ab + (size_t)ar*K + k0 + ac);
            As[ac+0][ar] = va.x; As[ac+1][ar] = va.y;
            As[ac+2][ar] = va.z; As[ac+3][ar] = va.w;
        }
        #pragma unroll
        for (int l = 0; l < 2; l++) {
            int s  = tid + l*256;
            int br = s >> 4, bc = (s & 15) << 2;
            *(float4*)(&Bs[br][bc]) = *(const float4*)(Bb + (size_t)(k0+br)*N + bc);
        }
        __syncthreads();
        #pragma unroll
        for (int kk = 0; kk < 32; kk++) {
            float4 a4 = *(const float4*)(&As[kk][ty << 2]);
            float4 b4 = *(const float4*)(&Bs[kk][tx << 2]);
            float a[4] = {a4.x, a4.y, a4.z, a4.w};
            float bb[4] = {b4.x, b4.y, b4.z, b4.w};
            #pragma unroll
            for (int i = 0; i < 4; i++)
                #pragma unroll
                for (int j = 0; j < 4; j++)
                    acc[i][j] += a[i] * bb[j];
        }
        __syncthreads();
    }
    #pragma unroll
    for (int i = 0; i < 4; i++) {
        int r = by*64 + ty*4 + i;
        #pragma unroll
        for (int j = 0; j < 4; j++)
            C[(size_t)r*N + bx*64 + tx*4 + j] = acc[i][j];
    }
}

// ===================== tf32 TC GEMM core ===================================
// BM=64, BN=64, BK=32, 128 threads = 4 warps (2m x 2n), warp tile 32x32.
// 3-stage cp.async pipeline, ONE __syncthreads per K-step.
// buf: As[3][64*40] @0 (7680), Bs[3][32*72] @7680 (6912) -> 14592 floats.
#define GA_ST 2560
#define GB_ST 2304

template<bool BIAS, bool RESID>
__device__ __forceinline__ void gemm_core(
    const float* __restrict__ Ab,    // A + by*64*K   (row stride K)
    const float* __restrict__ Bb,    // B + col0      (row stride N)
    const float* __restrict__ biasc,
    const float* __restrict__ resb,
    float* __restrict__ Cb,
    int N, int K, float* buf)
{
    float* As0 = buf;
    float* Bs0 = buf + 3*GA_ST;
    const int tid = threadIdx.x;
    const int wid = tid >> 5, wm = wid & 1, wn = wid >> 1;

    wmma::fragment<wmma::accumulator,16,16,8,float> acc[2][2];
    #pragma unroll
    for (int i = 0; i < 2; i++)
        #pragma unroll
        for (int j = 0; j < 2; j++) wmma::fill_fragment(acc[i][j], 0.0f);

    const int nk = K >> 5;

    // prefetch chunks 0,1
    #pragma unroll
    for (int s = 0; s < 2; s++) {
        float* As = As0 + s*GA_ST;
        float* Bs = Bs0 + s*GB_ST;
        const int k0 = s << 5;
        #pragma unroll
        for (int l = 0; l < 4; l++) {
            int idx = tid + l*128;
            int r = idx >> 3, c4 = (idx & 7) << 2;
            __pipeline_memcpy_async(&As[r*40 + c4], Ab + (size_t)r*K + k0 + c4, 16);
        }
        #pragma unroll
        for (int l = 0; l < 4; l++) {
            int idx = tid + l*128;
            int r = idx >> 4, c4 = (idx & 15) << 2;
            __pipeline_memcpy_async(&Bs[r*72 + c4], Bb + (size_t)(k0+r)*N + c4, 16);
        }
        __pipeline_commit();
    }

    for (int ik = 0; ik < nk; ik++) {
        __pipeline_wait_prior(1);       // chunk ik resident
        __syncthreads();                // all warps done with chunk ik-1
        if (ik + 2 < nk) {              // prefetch into slot (ik+2)%3 (= slot of ik-1)
            const int s = (ik+2) % 3;
            const int k0 = (ik+2) << 5;
            float* As = As0 + s*GA_ST;
            float* Bs = Bs0 + s*GB_ST;
            #pragma unroll
            for (int l = 0; l < 4; l++) {
                int idx = tid + l*128;
                int r = idx >> 3, c4 = (idx & 7) << 2;
                __pipeline_memcpy_async(&As[r*40 + c4], Ab + (size_t)r*K + k0 + c4, 16);
            }
            #pragma unroll
            for (int l = 0; l < 4; l++) {
                int idx = tid + l*128;
                int r = idx >> 4, c4 = (idx & 15) << 2;
                __pipeline_memcpy_async(&Bs[r*72 + c4], Bb + (size_t)(k0+r)*N + c4, 16);
            }
        }
        __pipeline_commit();            // always commit (keeps group count uniform)

        const float* As = As0 + (ik%3)*GA_ST;
        const float* Bs = Bs0 + (ik%3)*GB_ST;
        #pragma unroll
        for (int kk = 0; kk < 4; kk++) {
            wmma::fragment<wmma::matrix_a,16,16,8,wmma::precision::tf32,wmma::row_major> af[2];
            wmma::fragment<wmma::matrix_b,16,16,8,wmma::precision::tf32,wmma::row_major> bf[2];
            #pragma unroll
            for (int i = 0; i < 2; i++)
                wmma::load_matrix_sync(af[i], &As[(wm*32 + i*16)*40 + kk*8], 40);
            #pragma unroll
            for (int j = 0; j < 2; j++)
                wmma::load_matrix_sync(bf[j], &Bs[(kk*8)*72 + wn*32 + j*16], 72);
            #pragma unroll
            for (int i = 0; i < 2; i++)
                #pragma unroll
                for (int j = 0; j < 2; j++)
                    wmma::mma_sync(acc[i][j], af[i], bf[j], acc[i][j]);
        }
    }
    __syncthreads();

    float* St = buf;                    // stage [64][64]
    #pragma unroll
    for (int i = 0; i < 2; i++)
        #pragma unroll
        for (int j = 0; j < 2; j++)
            wmma::store_matrix_sync(&St[(wm*32 + i*16)*64 + wn*32 + j*16],
                                    acc[i][j], 64, wmma::mem_row_major);
    __syncthreads();
    #pragma unroll
    for (int l = 0; l < 8; l++) {
        int idx = tid + l*128;
        int r = idx >> 4, c4 = (idx & 15) << 2;
        float4 v = *(float4*)&St[r*64 + c4];
        if (BIAS) {
            float4 bb = *(const float4*)(biasc + c4);
            v.x += bb.x; v.y += bb.y; v.z += bb.z; v.w += bb.w;
        }
        if (RESID) {
            float4 rr = *(const float4*)(resb + (size_t)r*N + c4);
            v.x += rr.x; v.y += rr.y; v.z += rr.z; v.w += rr.w;
        }
        *(float4*)(Cb + (size_t)r*N + c4) = v;
    }
}

template<bool BIAS, bool RESID>
__global__ void __launch_bounds__(128)
gemm_tc(const float* __restrict__ A, const float* __restrict__ B,
        const float* __restrict__ bias, const float* __restrict__ res,
        float* __restrict__ C, int N, int K) {
    extern __shared__ float buf[];
    const int bx = blockIdx.x, by = blockIdx.y;
    gemm_core<BIAS,RESID>(A + (size_t)by*64*K, B + bx*64,
                          BIAS ? bias + bx*64 : nullptr,
                          RESID ? res + (size_t)by*64*N + bx*64 : nullptr,
                          C + (size_t)by*64*N + bx*64, N, K, buf);
}

// fused QKV: grid.x = 15 (3 weights x 5 col-tiles)
__global__ void __launch_bounds__(128)
qkv_tc(const float* __restrict__ A,
       const float* __restrict__ Wq, const float* __restrict__ Wk, const float* __restrict__ Wv,
       float* __restrict__ Oq, float* __restrict__ Ok, float* __restrict__ Ov) {
    extern __shared__ float buf[];
    const int bx = blockIdx.x, by = blockIdx.y;
    const int sel = bx / 5, cx = bx % 5;
    const float* B = (sel == 0) ? Wq : (sel == 1) ? Wk : Wv;
    float*       C = (sel == 0) ? Oq : (sel == 1) ? Ok : Ov;
    gemm_core<false,false>(A + (size_t)by*64*DIM, B + cx*64, nullptr, nullptr,
                           C + (size_t)by*64*DIM + cx*64, DIM, DIM, buf);
}

// ===================== ff1 + GEGLU fused (3-stage) =========================
// buf: As[3][2560] @0, Bx[3][2304] @7680, Bg[3][2304] @14592 -> 21504 floats
__global__ void __launch_bounds__(128)
ff1_geglu(const float* __restrict__ A, const float* __restrict__ W,
          const float* __restrict__ bias, float* __restrict__ Mid) {
    extern __shared__ float buf[];
    float* As0 = buf;
    float* Bx0 = buf + 3*GA_ST;
    float* Bg0 = buf + 3*GA_ST + 3*GB_ST;
    const int bx = blockIdx.x, by = blockIdx.y;
    const int tid = threadIdx.x, wid = tid >> 5, wm = wid & 1, wn = wid >> 1;
    const int NW = 2*FF;
    const float* Ab  = A + (size_t)by*64*DIM;
    const float* Bxb = W + bx*64;
    const float* Bgb = W + FF + bx*64;

    wmma::fragment<wmma::accumulator,16,16,8,float> accx[2][2], accg[2][2];
    #pragma unroll
    for (int i = 0; i < 2; i++)
        #pragma unroll
        for (int j = 0; j < 2; j++) {
            wmma::fill_fragment(accx[i][j], 0.0f);
            wmma::fill_fragment(accg[i][j], 0.0f);
        }

    #pragma unroll
    for (int s = 0; s < 2; s++) {
        const int k0 = s << 5;
        #pragma unroll
        for (int l = 0; l < 4; l++) {
            int idx = tid + l*128;
            int r = idx >> 3, c4 = (idx & 7) << 2;
            __pipeline_memcpy_async(&As0[s*GA_ST + r*40 + c4], Ab + (size_t)r*DIM + k0 + c4, 16);
        }
        #pragma unroll
        for (int l = 0; l < 4; l++) {
            int idx = tid + l*128;
            int r = idx >> 4, c4 = (idx & 15) << 2;
            __pipeline_memcpy_async(&Bx0[s*GB_ST + r*72 + c4], Bxb + (size_t)(k0+r)*NW + c4, 16);
            __pipeline_memcpy_async(&Bg0[s*GB_ST + r*72 + c4], Bgb + (size_t)(k0+r)*NW + c4, 16);
        }
        __pipeline_commit();
    }

    const int nk = DIM >> 5;   // 10
    for (int ik = 0; ik < nk; ik++) {
        __pipeline_wait_prior(1);
        __syncthreads();
        if (ik + 2 < nk) {
            const int s = (ik+2) % 3;
            const int k0 = (ik+2) << 5;
            #pragma unroll
            for (int l = 0; l < 4; l++) {
                int idx = tid + l*128;
                int r = idx >> 3, c4 = (idx & 7) << 2;
                __pipeline_memcpy_async(&As0[s*GA_ST + r*40 + c4], Ab + (size_t)r*DIM + k0 + c4, 16);
            }
            #pragma unroll
            for (int l = 0; l < 4; l++) {
                int idx = tid + l*128;
                int r = idx >> 4, c4 = (idx & 15) << 2;
                __pipeline_memcpy_async(&Bx0[s*GB_ST + r*72 + c4], Bxb + (size_t)(k0+r)*NW + c4, 16);
                __pipeline_memcpy_async(&Bg0[s*GB_ST + r*72 + c4], Bgb + (size_t)(k0+r)*NW + c4, 16);
            }
        }
        __pipeline_commit();

        const float* As = As0 + (ik%3)*GA_ST;
        const float* Bx = Bx0 + (ik%3)*GB_ST;
        const float* Bg = Bg0 + (ik%3)*GB_ST;
        #pragma unroll
        for (int kk = 0; kk < 4; kk++) {
            wmma::fragment<wmma::matrix_a,16,16,8,wmma::precision::tf32,wmma::row_major> af[2];
            wmma::fragment<wmma::matrix_b,16,16,8,wmma::precision::tf32,wmma::row_major> bfx[2], bfg[2];
            #pragma unroll
            for (int i = 0; i < 2; i++)
                wmma::load_matrix_sync(af[i], &As[(wm*32 + i*16)*40 + kk*8], 40);
            #pragma unroll
            for (int j = 0; j < 2; j++) {
                wmma::load_matrix_sync(bfx[j], &Bx[(kk*8)*72 + wn*32 + j*16], 72);
                wmma::load_matrix_sync(bfg[j], &Bg[(kk*8)*72 + wn*32 + j*16], 72);
            }
            #pragma unroll
            for (int i = 0; i < 2; i++)
                #pragma unroll
                for (int j = 0; j < 2; j++) {
                    wmma::mma_sync(accx[i][j], af[i], bfx[j], accx[i][j]);
                    wmma::mma_sync(accg[i][j], af[i], bfg[j], accg[i][j]);
                }
        }
    }
    __syncthreads();

    float* Stx = buf;            // [64][64]
    float* Stg = buf + 4096;     // [64][64]
    #pragma unroll
    for (int i = 0; i < 2; i++)
        #pragma unroll
        for (int j = 0; j < 2; j++) {
            wmma::store_matrix_sync(&Stx[(wm*32 + i*16)*64 + wn*32 + j*16], accx[i][j], 64, wmma::mem_row_major);
            wmma::store_matrix_sync(&Stg[(wm*32 + i*16)*64 + wn*32 + j*16], accg[i][j], 64, wmma::mem_row_major);
        }
    __syncthreads();
    #pragma unroll
    for (int l = 0; l < 8; l++) {
        int idx = tid + l*128;
        int r = idx >> 4, c4 = (idx & 15) << 2;
        float4 xv = *(float4*)&Stx[r*64 + c4];
        float4 gv = *(float4*)&Stg[r*64 + c4];
        float4 bxv = *(const float4*)(bias + bx*64 + c4);
        float4 bgv = *(const float4*)(bias + FF + bx*64 + c4);
        float xa[4] = {xv.x+bxv.x, xv.y+bxv.y, xv.z+bxv.z, xv.w+bxv.w};
        float ga[4] = {gv.x+bgv.x, gv.y+bgv.y, gv.z+bgv.z, gv.w+bgv.w};
        float4 o;
        float* op = (float*)&o;
        #pragma unroll
        for (int e = 0; e < 4; e++) {
            float g = ga[e];
            op[e] = xa[e] * (0.5f * g * (1.f + erff(g * 0.70710678118654752f)));
        }
        *(float4*)(Mid + (size_t)(by*64 + r)*FF + bx*64 + c4) = o;
    }
}

// ===================== tensor-core flash attention =========================
// 128-query tile, 256 threads = 8 warps; warp w owns query rows [w*16, w*16+16).
// S computed per-warp (16x64), exp applied IN-REGISTER on the accumulator,
// P staged in per-warp private smem, row-sums via ones-column in V (col 40).
// 3-stage K/V cp.async pipeline; ONE __syncthreads per key-tile.
__global__ void __launch_bounds__(256)
flash_tc(const float* __restrict__ Q, const float* __restrict__ K,
         const float* __restrict__ V, float* __restrict__ O) {
    extern __shared__ float sm[];
    float* Qs  = sm;                   // [128][48]
    float* Ks0 = Qs  + 128*48;         // 3 x [64][48]
    float* Vs0 = Ks0 + 3*64*48;        // 3 x [64][48]
    float* Ps  = Vs0 + 3*64*48;        // 8 x [16][72] per-warp private

    const int tid = threadIdx.x, wid = tid >> 5;
    const int b = blockIdx.y >> 3, h = blockIdx.y & 7;
    const int q0 = blockIdx.x * 128;
    const size_t base = ((size_t)b*LQ)*DIM + h*HD;
    const float scale = 0.158113883008419f;    // 1/sqrt(40)
    float* Pw = Ps + wid*16*72;

    // pad init: K cols 40..47 = 0 (all 3 stages); V col40 = 1 (ones trick), 41..47 = 0
    for (int r = tid; r < 192; r += 256) {
        float* kr = &Ks0[r*48];
        float* vr = &Vs0[r*48];
        #pragma unroll
        for (int c = 40; c < 48; c++) kr[c] = 0.f;
        vr[40] = 1.0f;
        #pragma unroll
        for (int c = 41; c < 48; c++) vr[c] = 0.f;
    }
    // Q pad + load (scaled)
    {
        int rr = tid >> 1, c = 40 + ((tid & 1) << 2);
        float4 z4 = {0.f,0.f,0.f,0.f};
        *(float4*)&Qs[rr*48 + c] = z4;
    }
    #pragma unroll
    for (int l = 0; l < 5; l++) {
        int idx = tid + l*256;
        int r = idx/10, c4 = (idx - r*10)*4;
        float4 v = *(const float4*)(Q + base + (size_t)(q0+r)*DIM + c4);
        v.x *= scale; v.y *= scale; v.z *= scale; v.w *= scale;
        *(float4*)&Qs[r*48 + c4] = v;
    }

    wmma::fragment<wmma::accumulator,16,16,8,float> oacc[3];
    #pragma unroll
    for (int j = 0; j < 3; j++) wmma::fill_fragment(oacc[j], 0.0f);

    // prefetch key-tiles 0,1 (each: K 640 f4 + V 640 f4; 256 thr -> 5 iters)
    #pragma unroll
    for (int s = 0; s < 2; s++) {
        const int kt = s*64;
        #pragma unroll
        for (int l = 0; l < 5; l++) {
            int idx = tid + l*256;
            int ch = (idx < 640) ? idx : idx - 640;
            int r = ch/10, c4 = (ch - r*10)*4;
            const float* src = ((idx < 640) ? K : V) + base + (size_t)(kt+r)*DIM + c4;
            float* dst = ((idx < 640) ? Ks0 + s*3072 : Vs0 + s*3072) + r*48 + c4;
            __pipeline_memcpy_async(dst, src, 16);
        }
        __pipeline_commit();
    }

    const int NT = LQ/64;   // 32
    for (int it = 0; it < NT; it++) {
        __pipeline_wait_prior(1);
        __syncthreads();
        if (it + 2 < NT) {
            const int s = (it+2) % 3;
            const int kt = (it+2)*64;
            #pragma unroll
            for (int l = 0; l < 5; l++) {
                int idx = tid + l*256;
                int ch = (idx < 640) ? idx : idx - 640;
                int r = ch/10, c4 = (ch - r*10)*4;
                const float* src = ((idx < 640) ? K : V) + base + (size_t)(kt+r)*DIM + c4;
                float* dst = ((idx < 640) ? Ks0 + s*3072 : Vs0 + s*3072) + r*48 + c4;
                __pipeline_memcpy_async(dst, src, 16);
            }
        }
        __pipeline_commit();

        const float* Kd = Ks0 + (it%3)*3072;
        const float* Vd = Vs0 + (it%3)*3072;

        // S[16,64] = Q_band @ Kd^T  (per-warp, no cross-warp deps)
        wmma::fragment<wmma::accumulator,16,16,8,float> sacc[4];
        #pragma unroll
        for (int j = 0; j < 4; j++) wmma::fill_fragment(sacc[j], 0.0f);
        #pragma unroll
        for (int kk = 0; kk < 6; kk++) {
            wmma::fragment<wmma::matrix_a,16,16,8,wmma::precision::tf32,wmma::row_major> af;
            wmma::load_matrix_sync(af, &Qs[(wid*16)*48 + kk*8], 48);
            #pragma unroll
            for (int j = 0; j < 4; j++) {
                wmma::fragment<wmma::matrix_b,16,16,8,wmma::precision::tf32,wmma::col_major> bf;
                wmma::load_matrix_sync(bf, &Kd[(j*16)*48 + kk*8], 48);
                wmma::mma_sync(sacc[j], af, bf, sacc[j]);
            }
        }
        // exp in-register, stage P in private smem
        #pragma unroll
        for (int j = 0; j < 4; j++) {
            #pragma unroll
            for (int t = 0; t < sacc[j].num_elements; t++)
                sacc[j].x[t] = __expf(sacc[j].x[t]);
            wmma::store_matrix_sync(&Pw[j*16], sacc[j], 72, wmma::mem_row_major);
        }
        // O[16,48] += P[16,64] @ V[64,48]  (col 40 of V = 1 -> accumulates l)
        #pragma unroll
        for (int kk = 0; kk < 8; kk++) {
            wmma::fragment<wmma::matrix_a,16,16,8,wmma::precision::tf32,wmma::row_major> af;
            wmma::load_matrix_sync(af, &Pw[kk*8], 72);
            #pragma unroll
            for (int j = 0; j < 3; j++) {
                wmma::fragment<wmma::matrix_b,16,16,8,wmma::precision::tf32,wmma::row_major> bf;
                wmma::load_matrix_sync(bf, &Vd[(kk*8)*48 + j*16], 48);
                wmma::mma_sync(oacc[j], af, bf, oacc[j]);
            }
        }
    }

    // epilogue: per-warp private staging (reuse Pw), divide by col 40
    float* Ow = Pw;   // [16][48]
    #pragma unroll
    for (int j = 0; j < 3; j++)
        wmma::store_matrix_sync(&Ow[j*16], oacc[j], 48, wmma::mem_row_major);
    __syncwarp();
    const int lane = tid & 31;
    #pragma unroll
    for (int l = 0; l < 5; l++) {
        int idx = lane + l*32;          // 16 rows x 10 f4 = 160
        int r = idx/10, c4 = (idx - r*10)*4;
        float inv = 1.0f / Ow[r*48 + 40];
        float4 v = *(float4*)&Ow[r*48 + c4];
        v.x *= inv; v.y *= inv; v.z *= inv; v.w *= inv;
        *(float4*)(O + base + (size_t)(q0 + wid*16 + r)*DIM + c4) = v;
    }
}

// ---------------------------------------------------------------------------
extern "C" void kernel_launch(void* const* d_in, const int* in_sizes, int n_in,
                              void* d_out, int out_size) {
    (void)in_sizes; (void)n_in; (void)out_size;
    const float* x    = (const float*)d_in[0];
    const float* ln1g = (const float*)d_in[2];
    const float* ln1b = (const float*)d_in[3];
    const float* wq1  = (const float*)d_in[4];
    const float* wk1  = (const float*)d_in[5];
    const float* wv1  = (const float*)d_in[6];
    const float* wo1  = (const float*)d_in[7];
    const float* bo1  = (const float*)d_in[8];
    const float* ln2g = (const float*)d_in[9];
    const float* ln2b = (const float*)d_in[10];
    const float* wvh  = (const float*)d_in[13];
    const float* wo2  = (const float*)d_in[14];
    const float* bo2  = (const float*)d_in[15];
    const float* ln3g = (const float*)d_in[16];
    const float* ln3b = (const float*)d_in[17];
    const float* wff1 = (const float*)d_in[18];
    const float* bff1 = (const float*)d_in[19];
    const float* wff2 = (const float*)d_in[20];
    const float* bff2 = (const float*)d_in[21];
    float* out = (float*)d_out;

    float *p_h, *p_q, *p_k, *p_v, *p_at, *p_x1, *p_x2, *p_wc, *p_mid;
    cudaGetSymbolAddress((void**)&p_h,   g_h);
    cudaGetSymbolAddress((void**)&p_q,   g_q);
    cudaGetSymbolAddress((void**)&p_k,   g_k);
    cudaGetSymbolAddress((void**)&p_v,   g_v);
    cudaGetSymbolAddress((void**)&p_at,  g_at);
    cudaGetSymbolAddress((void**)&p_x1,  g_x1);
    cudaGetSymbolAddress((void**)&p_x2,  g_x2);
    cudaGetSymbolAddress((void**)&p_wc,  g_wc);
    cudaGetSymbolAddress((void**)&p_mid, g_mid);

    const int gemm_smem  = (3*GA_ST + 3*GB_ST)*4;            // 58368
    const int ff1_smem   = (3*GA_ST + 6*GB_ST)*4;            // 85248
    const int flash_smem = (128*48 + 6*64*48 + 8*16*72)*4;   // 135168

    static bool attr_set = false;
    if (!attr_set) {
        cudaFuncSetAttribute(gemm_tc<true,true>,   cudaFuncAttributeMaxDynamicSharedMemorySize, gemm_smem);
        cudaFuncSetAttribute(gemm_tc<false,false>, cudaFuncAttributeMaxDynamicSharedMemorySize, gemm_smem);
        cudaFuncSetAttribute(qkv_tc,               cudaFuncAttributeMaxDynamicSharedMemorySize, gemm_smem);
        cudaFuncSetAttribute(ff1_geglu,            cudaFuncAttributeMaxDynamicSharedMemorySize, ff1_smem);
        cudaFuncSetAttribute(flash_tc,             cudaFuncAttributeMaxDynamicSharedMemorySize, flash_smem);
        attr_set = true;
    }

    const dim3 gTok(DIM/64, M_TOK/64);        // (5, 64) = 320 blocks

    // ---- block 1: self-attention ----
    ln_kernel<<<M_TOK, DIM>>>(x, ln1g, ln1b, p_h);
    qkv_tc<<<dim3(15, M_TOK/64), 128, gemm_smem>>>(p_h, wq1, wk1, wv1, p_q, p_k, p_v);
    flash_tc<<<dim3(LQ/128, BATCH*NH), 256, flash_smem>>>(p_q, p_k, p_v, p_at);
    gemm_tc<true,true><<<gTok, 128, gemm_smem>>>(p_at, wo1, bo1, x, p_x1, DIM, DIM);

    // ---- block 2: cross-attn collapses to  x2 = x1 + LN(x1) @ (wvh@wo2) + bo2
    gemm_f32<<<dim3(5,5), 256>>>(wvh, wo2, p_wc, DIM, DIM, DIM);
    ln_kernel<<<M_TOK, DIM>>>(p_x1, ln2g, ln2b, p_h);
    gemm_tc<true,true><<<gTok, 128, gemm_smem>>>(p_h, p_wc, bo2, p_x1, p_x2, DIM, DIM);

    // ---- block 3: GEGLU FF ----
    ln_kernel<<<M_TOK, DIM>>>(p_x2, ln3g, ln3b, p_h);
    ff1_geglu<<<dim3(FF/64, M_TOK/64), 128, ff1_smem>>>(p_h, wff1, bff1, p_mid);
    gemm_tc<true,true><<<gTok, 128, gemm_smem>>>(p_mid, wff2, bff2, p_x2, out, DIM, FF);
}

// round 10
// speedup vs baseline: 2.4918x; 2.4918x over previous
#include <cuda_runtime.h>
#include <cuda_pipeline.h>
#include <cuda_bf16.h>
#include <mma.h>
#include <math.h>
#include <stddef.h>

using namespace nvcuda;
typedef __nv_bfloat16 bf16;

#define LQ    2048
#define BATCH 2
#define DIM   320
#define NH    8
#define HD    40
#define FF    1280
#define M_TOK (BATCH*LQ)   /* 4096 */

#define GA_EL 5120   /* 128x40 bf16 A stage */
#define GB_EL 2304   /* 32x72  bf16 B stage */

// -------------------- scratch (device globals) -----------------------------
__device__ bf16  g_h  [M_TOK*DIM];
__device__ bf16  g_q  [M_TOK*DIM];
__device__ bf16  g_k  [M_TOK*DIM];
__device__ bf16  g_v  [M_TOK*DIM];
__device__ bf16  g_at [M_TOK*DIM];
__device__ float g_x1 [M_TOK*DIM];
__device__ float g_x2 [M_TOK*DIM];
__device__ bf16  g_wc [DIM*DIM];
__device__ bf16  g_mid[M_TOK*FF];
__device__ bf16  g_wb [4*DIM*DIM + DIM*2*FF + FF*DIM];   // converted weights

#define WB_Q   0
#define WB_K   (DIM*DIM)
#define WB_V   (2*DIM*DIM)
#define WB_O   (3*DIM*DIM)
#define WB_FF1 (4*DIM*DIM)
#define WB_FF2 (4*DIM*DIM + DIM*2*FF)
#define WB_TOT (4*DIM*DIM + DIM*2*FF + FF*DIM)   // 1,638,400

// -------------------- weight fp32 -> bf16 conversion -----------------------
__global__ void convert_w(const float* __restrict__ wq, const float* __restrict__ wk,
                          const float* __restrict__ wv, const float* __restrict__ wo,
                          const float* __restrict__ wf1, const float* __restrict__ wf2,
                          bf16* __restrict__ out) {
    int idx = blockIdx.x * 256 + threadIdx.x;
    if (idx >= WB_TOT) return;
    float v;
    if (idx < WB_FF1) {
        int w = idx / (DIM*DIM), r = idx % (DIM*DIM);
        const float* src = (w == 0) ? wq : (w == 1) ? wk : (w == 2) ? wv : wo;
        v = src[r];
    } else if (idx < WB_FF2) {
        v = wf1[idx - WB_FF1];
    } else {
        v = wf2[idx - WB_FF2];
    }
    out[idx] = __float2bfloat16(v);
}

// -------------------- LayerNorm (fp32 in -> bf16 out) ----------------------
__global__ void ln_kernel(const float* __restrict__ x, const float* __restrict__ g,
                          const float* __restrict__ b, bf16* __restrict__ out) {
    int row = blockIdx.x;
    int t   = threadIdx.x;           // 0..319
    float v = x[(size_t)row*DIM + t];
    float s = v, sq = v*v;
    #pragma unroll
    for (int o = 16; o > 0; o >>= 1) {
        s  += __shfl_xor_sync(0xffffffff, s,  o);
        sq += __shfl_xor_sync(0xffffffff, sq, o);
    }
    __shared__ float ws[10], wq[10];
    __shared__ float mean_s, rstd_s;
    int w = t >> 5;
    if ((t & 31) == 0) { ws[w] = s; wq[w] = sq; }
    __syncthreads();
    if (t == 0) {
        float S = 0.f, Q = 0.f;
        #pragma unroll
        for (int i = 0; i < 10; i++) { S += ws[i]; Q += wq[i]; }
        float m   = S * (1.0f/DIM);
        float var = Q * (1.0f/DIM) - m*m;
        mean_s = m;
        rstd_s = rsqrtf(var + 1e-5f);
    }
    __syncthreads();
    out[(size_t)row*DIM + t] = __float2bfloat16((v - mean_s) * rstd_s * g[t] + b[t]);
}

// -------------------- small fp32 GEMM: wc = wvh @ wo2 (bf16 out) -----------
__global__ void __launch_bounds__(256)
gemm_f32(const float* __restrict__ A, const float* __restrict__ B,
         bf16* __restrict__ C, int M, int N, int K) {
    __shared__ float As[32][64];
    __shared__ float Bs[32][64];
    const int tid = threadIdx.x;
    const int bx = blockIdx.x, by = blockIdx.y;
    const int ty = tid >> 4, tx = tid & 15;
    float acc[4][4] = {};
    const float* Ab = A + (size_t)by * 64 * K;
    const float* Bb = B + (size_t)bx * 64;
    for (int k0 = 0; k0 < K; k0 += 32) {
        #pragma unroll
        for (int l = 0; l < 2; l++) {
            int s  = tid + l*256;
            int ar = s >> 3, ac = (s & 7) << 2;
            float4 va = *(const float4*)(Ab + (size_t)ar*K + k0 + ac);
            As[ac+0][ar] = va.x; As[ac+1][ar] = va.y;
            As[ac+2][ar] = va.z; As[ac+3][ar] = va.w;
        }
        #pragma unroll
        for (int l = 0; l < 2; l++) {
            int s  = tid + l*256;
            int br = s >> 4, bc = (s & 15) << 2;
            *(float4*)(&Bs[br][bc]) = *(const float4*)(Bb + (size_t)(k0+br)*N + bc);
        }
        __syncthreads();
        #pragma unroll
        for (int kk = 0; kk < 32; kk++) {
            float4 a4 = *(const float4*)(&As[kk][ty << 2]);
            float4 b4 = *(const float4*)(&Bs[kk][tx << 2]);
            float a[4] = {a4.x, a4.y, a4.z, a4.w};
            float bb[4] = {b4.x, b4.y, b4.z, b4.w};
            #pragma unroll
            for (int i = 0; i < 4; i++)
                #pragma unroll
                for (int j = 0; j < 4; j++)
                    acc[i][j] += a[i] * bb[j];
        }
        __syncthreads();
    }
    #pragma unroll
    for (int i = 0; i < 4; i++) {
        int r = by*64 + ty*4 + i;
        #pragma unroll
        for (int j = 0; j < 4; j++)
            C[(size_t)r*N + bx*64 + tx*4 + j] = __float2bfloat16(acc[i][j]);
    }
}

// ===================== bf16 TC GEMM core ===================================
// BM=128, BN=64, BK=32. 256 threads = 8 warps (4m x 2n), warp tile 32x32.
// wmma 16x16x16 bf16, fp32 accum. Double-buffered cp.async (R6 pattern).
template<bool BIAS, bool RESID, bool OBF>
__device__ __forceinline__ void gemm_core(
    const bf16* __restrict__ Ab,     // A + by*128*K  (row stride K)
    const bf16* __restrict__ Bb,     // B + col0      (row stride N)
    const float* __restrict__ biasc,
    const float* __restrict__ resb,
    void* __restrict__ Cb,
    int N, int K, char* smemraw)
{
    bf16* As0 = (bf16*)smemraw;          // 2 x GA_EL
    bf16* Bs0 = As0 + 2*GA_EL;           // 2 x GB_EL
    const int tid = threadIdx.x;
    const int wid = tid >> 5, wm = wid & 3, wn = wid >> 2;

    wmma::fragment<wmma::accumulator,16,16,16,float> acc[2][2];
    #pragma unroll
    for (int i = 0; i < 2; i++)
        #pragma unroll
        for (int j = 0; j < 2; j++) wmma::fill_fragment(acc[i][j], 0.0f);

    // prefetch stage 0
    {
        #pragma unroll
        for (int l = 0; l < 2; l++) {        // A: 512 chunks of 8 bf16
            int idx = tid + l*256;
            int r = idx >> 2, c8 = (idx & 3) << 3;
            __pipeline_memcpy_async(&As0[r*40 + c8], Ab + (size_t)r*K + c8, 16);
        }
        {                                     // B: 256 chunks
            int r = tid >> 3, c8 = (tid & 7) << 3;
            __pipeline_memcpy_async(&Bs0[r*72 + c8], Bb + (size_t)r*N + c8, 16);
        }
        __pipeline_commit();
    }

    const int nk = K >> 5;
    for (int ik = 0; ik < nk; ik++) {
        const int cur = ik & 1;
        if (ik + 1 < nk) {
            const int k0 = (ik + 1) << 5;
            bf16* As = As0 + (cur^1)*GA_EL;
            bf16* Bs = Bs0 + (cur^1)*GB_EL;
            #pragma unroll
            for (int l = 0; l < 2; l++) {
                int idx = tid + l*256;
                int r = idx >> 2, c8 = (idx & 3) << 3;
                __pipeline_memcpy_async(&As[r*40 + c8], Ab + (size_t)r*K + k0 + c8, 16);
            }
            {
                int r = tid >> 3, c8 = (tid & 7) << 3;
                __pipeline_memcpy_async(&Bs[r*72 + c8], Bb + (size_t)(k0+r)*N + c8, 16);
            }
            __pipeline_commit();
            __pipeline_wait_prior(1);
        } else {
            __pipeline_wait_prior(0);
        }
        __syncthreads();
        const bf16* As = As0 + cur*GA_EL;
        const bf16* Bs = Bs0 + cur*GB_EL;
        #pragma unroll
        for (int kk = 0; kk < 2; kk++) {
            wmma::fragment<wmma::matrix_a,16,16,16,bf16,wmma::row_major> af[2];
            wmma::fragment<wmma::matrix_b,16,16,16,bf16,wmma::row_major> bf[2];
            #pragma unroll
            for (int i = 0; i < 2; i++)
                wmma::load_matrix_sync(af[i], &As[(wm*32 + i*16)*40 + kk*16], 40);
            #pragma unroll
            for (int j = 0; j < 2; j++)
                wmma::load_matrix_sync(bf[j], &Bs[(kk*16)*72 + wn*32 + j*16], 72);
            #pragma unroll
            for (int i = 0; i < 2; i++)
                #pragma unroll
                for (int j = 0; j < 2; j++)
                    wmma::mma_sync(acc[i][j], af[i], bf[j], acc[i][j]);
        }
        __syncthreads();
    }

    // epilogue via fp32 smem stage [128][64] (overlaps operand buffers)
    float* St = (float*)smemraw;
    #pragma unroll
    for (int i = 0; i < 2; i++)
        #pragma unroll
        for (int j = 0; j < 2; j++)
            wmma::store_matrix_sync(&St[(wm*32 + i*16)*64 + wn*32 + j*16],
                                    acc[i][j], 64, wmma::mem_row_major);
    __syncthreads();
    #pragma unroll
    for (int l = 0; l < 8; l++) {
        int idx = tid + l*256;
        int r = idx >> 4, c4 = (idx & 15) << 2;
        float4 v = *(float4*)&St[r*64 + c4];
        if (BIAS) {
            float4 bb = *(const float4*)(biasc + c4);
            v.x += bb.x; v.y += bb.y; v.z += bb.z; v.w += bb.w;
        }
        if (RESID) {
            float4 rr = *(const float4*)(resb + (size_t)r*N + c4);
            v.x += rr.x; v.y += rr.y; v.z += rr.z; v.w += rr.w;
        }
        if (OBF) {
            bf16* Co = (bf16*)Cb + (size_t)r*N + c4;
            __nv_bfloat162 p0; p0.x = __float2bfloat16(v.x); p0.y = __float2bfloat16(v.y);
            __nv_bfloat162 p1; p1.x = __float2bfloat16(v.z); p1.y = __float2bfloat16(v.w);
            *(__nv_bfloat162*)(Co)     = p0;
            *(__nv_bfloat162*)(Co + 2) = p1;
        } else {
            *(float4*)((float*)Cb + (size_t)r*N + c4) = v;
        }
    }
}

template<bool BIAS, bool RESID>
__global__ void __launch_bounds__(256)
gemm_tc(const bf16* __restrict__ A, const bf16* __restrict__ B,
        const float* __restrict__ bias, const float* __restrict__ res,
        float* __restrict__ C, int N, int K) {
    extern __shared__ char smemraw[];
    const int bx = blockIdx.x, by = blockIdx.y;
    gemm_core<BIAS,RESID,false>(A + (size_t)by*128*K, B + bx*64,
                                BIAS ? bias + bx*64 : nullptr,
                                RESID ? res + (size_t)by*128*N + bx*64 : nullptr,
                                C + (size_t)by*128*N + bx*64, N, K, smemraw);
}

// fused QKV (bf16 out): grid.x = 15 (3 weights x 5 col-tiles)
__global__ void __launch_bounds__(256)
qkv_tc(const bf16* __restrict__ A, const bf16* __restrict__ WB,
       bf16* __restrict__ Oq, bf16* __restrict__ Ok, bf16* __restrict__ Ov) {
    extern __shared__ char smemraw[];
    const int bx = blockIdx.x, by = blockIdx.y;
    const int sel = bx / 5, cx = bx % 5;
    const bf16* B = WB + ((sel == 0) ? WB_Q : (sel == 1) ? WB_K : WB_V);
    bf16*       C = (sel == 0) ? Oq : (sel == 1) ? Ok : Ov;
    gemm_core<false,false,true>(A + (size_t)by*128*DIM, B + cx*64, nullptr, nullptr,
                                C + (size_t)by*128*DIM + cx*64, DIM, DIM, smemraw);
}

// ===================== ff1 + GEGLU fused (bf16, double-buffered) ===========
__global__ void __launch_bounds__(256)
ff1_geglu(const bf16* __restrict__ A, const bf16* __restrict__ W,
          const float* __restrict__ bias, bf16* __restrict__ Mid) {
    extern __shared__ char smemraw[];
    bf16* As0 = (bf16*)smemraw;             // 2 x GA_EL
    bf16* Bx0 = As0 + 2*GA_EL;              // 2 x GB_EL
    bf16* Bg0 = Bx0 + 2*GB_EL;              // 2 x GB_EL
    const int bx = blockIdx.x, by = blockIdx.y;
    const int tid = threadIdx.x, wid = tid >> 5, wm = wid & 3, wn = wid >> 2;
    const int NW = 2*FF;
    const bf16* Ab  = A + (size_t)by*128*DIM;
    const bf16* Bxb = W + bx*64;
    const bf16* Bgb = W + FF + bx*64;

    wmma::fragment<wmma::accumulator,16,16,16,float> accx[2][2], accg[2][2];
    #pragma unroll
    for (int i = 0; i < 2; i++)
        #pragma unroll
        for (int j = 0; j < 2; j++) {
            wmma::fill_fragment(accx[i][j], 0.0f);
            wmma::fill_fragment(accg[i][j], 0.0f);
        }

    {
        #pragma unroll
        for (int l = 0; l < 2; l++) {
            int idx = tid + l*256;
            int r = idx >> 2, c8 = (idx & 3) << 3;
            __pipeline_memcpy_async(&As0[r*40 + c8], Ab + (size_t)r*DIM + c8, 16);
        }
        {
            int r = tid >> 3, c8 = (tid & 7) << 3;
            __pipeline_memcpy_async(&Bx0[r*72 + c8], Bxb + (size_t)r*NW + c8, 16);
            __pipeline_memcpy_async(&Bg0[r*72 + c8], Bgb + (size_t)r*NW + c8, 16);
        }
        __pipeline_commit();
    }

    const int nk = DIM >> 5;   // 10
    for (int ik = 0; ik < nk; ik++) {
        const int cur = ik & 1;
        if (ik + 1 < nk) {
            const int k0 = (ik + 1) << 5;
            bf16* As = As0 + (cur^1)*GA_EL;
            bf16* Bx = Bx0 + (cur^1)*GB_EL;
            bf16* Bg = Bg0 + (cur^1)*GB_EL;
            #pragma unroll
            for (int l = 0; l < 2; l++) {
                int idx = tid + l*256;
                int r = idx >> 2, c8 = (idx & 3) << 3;
                __pipeline_memcpy_async(&As[r*40 + c8], Ab + (size_t)r*DIM + k0 + c8, 16);
            }
            {
                int r = tid >> 3, c8 = (tid & 7) << 3;
                __pipeline_memcpy_async(&Bx[r*72 + c8], Bxb + (size_t)(k0+r)*NW + c8, 16);
                __pipeline_memcpy_async(&Bg[r*72 + c8], Bgb + (size_t)(k0+r)*NW + c8, 16);
            }
            __pipeline_commit();
            __pipeline_wait_prior(1);
        } else {
            __pipeline_wait_prior(0);
        }
        __syncthreads();
        const bf16* As = As0 + cur*GA_EL;
        const bf16* Bx = Bx0 + cur*GB_EL;
        const bf16* Bg = Bg0 + cur*GB_EL;
        #pragma unroll
        for (int kk = 0; kk < 2; kk++) {
            wmma::fragment<wmma::matrix_a,16,16,16,bf16,wmma::row_major> af[2];
            wmma::fragment<wmma::matrix_b,16,16,16,bf16,wmma::row_major> bfx[2], bfg[2];
            #pragma unroll
            for (int i = 0; i < 2; i++)
                wmma::load_matrix_sync(af[i], &As[(wm*32 + i*16)*40 + kk*16], 40);
            #pragma unroll
            for (int j = 0; j < 2; j++) {
                wmma::load_matrix_sync(bfx[j], &Bx[(kk*16)*72 + wn*32 + j*16], 72);
                wmma::load_matrix_sync(bfg[j], &Bg[(kk*16)*72 + wn*32 + j*16], 72);
            }
            #pragma unroll
            for (int i = 0; i < 2; i++)
                #pragma unroll
                for (int j = 0; j < 2; j++) {
                    wmma::mma_sync(accx[i][j], af[i], bfx[j], accx[i][j]);
                    wmma::mma_sync(accg[i][j], af[i], bfg[j], accg[i][j]);
                }
        }
        __syncthreads();
    }

    float* Stx = (float*)smemraw;          // [128][64]
    float* Stg = Stx + 8192;               // [128][64]
    #pragma unroll
    for (int i = 0; i < 2; i++)
        #pragma unroll
        for (int j = 0; j < 2; j++) {
            wmma::store_matrix_sync(&Stx[(wm*32 + i*16)*64 + wn*32 + j*16], accx[i][j], 64, wmma::mem_row_major);
            wmma::store_matrix_sync(&Stg[(wm*32 + i*16)*64 + wn*32 + j*16], accg[i][j], 64, wmma::mem_row_major);
        }
    __syncthreads();
    #pragma unroll
    for (int l = 0; l < 8; l++) {
        int idx = tid + l*256;
        int r = idx >> 4, c4 = (idx & 15) << 2;
        float4 xv = *(float4*)&Stx[r*64 + c4];
        float4 gv = *(float4*)&Stg[r*64 + c4];
        float4 bxv = *(const float4*)(bias + bx*64 + c4);
        float4 bgv = *(const float4*)(bias + FF + bx*64 + c4);
        float xa[4] = {xv.x+bxv.x, xv.y+bxv.y, xv.z+bxv.z, xv.w+bxv.w};
        float ga[4] = {gv.x+bgv.x, gv.y+bgv.y, gv.z+bgv.z, gv.w+bgv.w};
        bf16 ov[4];
        #pragma unroll
        for (int e = 0; e < 4; e++) {
            float g = ga[e];
            ov[e] = __float2bfloat16(xa[e] * (0.5f * g * (1.f + erff(g * 0.70710678118654752f))));
        }
        bf16* Mo = Mid + (size_t)(by*128 + r)*FF + bx*64 + c4;
        __nv_bfloat162 p0; p0.x = ov[0]; p0.y = ov[1];
        __nv_bfloat162 p1; p1.x = ov[2]; p1.y = ov[3];
        *(__nv_bfloat162*)(Mo)     = p0;
        *(__nv_bfloat162*)(Mo + 2) = p1;
    }
}

// ===================== bf16 tensor-core flash attention ====================
// 128-query tile, 256 threads = 8 warps. S warps 4m x 2n; exp in fp32 with
// scale folded into exp; P staged bf16; P@V warp w owns rows w*16.
// K/V double-buffered via cp.async (R6 pattern).
__global__ void __launch_bounds__(256)
flash_tc(const bf16* __restrict__ Q, const bf16* __restrict__ K,
         const bf16* __restrict__ V, bf16* __restrict__ O) {
    extern __shared__ char smc[];
    bf16*  Qs   = (bf16*)smc;              // [128][48]
    bf16*  Ks0  = Qs  + 128*48;            // 2 x [64][48]
    bf16*  Vs0  = Ks0 + 2*64*48;           // 2 x [64][48]
    float* Ss   = (float*)(Vs0 + 2*64*48); // [128][72] fp32 (O stage at end)
    bf16*  Ps   = (bf16*)(Ss + 128*72);    // [128][72] bf16
    float* lsum = (float*)(Ps + 128*72);   // [128]

    const int tid = threadIdx.x, wid = tid >> 5;
    const int b = blockIdx.y >> 3, h = blockIdx.y & 7;
    const int q0 = blockIdx.x * 128;
    const size_t base = ((size_t)b*LQ)*DIM + h*HD;
    const float scale = 0.158113883008419f;    // 1/sqrt(40)

    if (tid < 128) {
        lsum[tid] = 0.f;
        // zero pad cols 40..47 (16B per row): Qs 128 rows, Ks/Vs 128 rows (2 stages)
        uint4 z = {0u,0u,0u,0u};
        *(uint4*)&Qs [tid*48 + 40] = z;
        *(uint4*)&Ks0[tid*48 + 40] = z;
        *(uint4*)&Vs0[tid*48 + 40] = z;
    }
    // Q load (raw bf16; scale folded into exp)
    #pragma unroll
    for (int l = 0; l < 3; l++) {
        int idx = tid + l*256;
        if (idx < 640) {
            int r = idx/5, c8 = (idx - r*5)*8;
            *(uint4*)&Qs[r*48 + c8] = *(const uint4*)(Q + base + (size_t)(q0+r)*DIM + c8);
        }
    }

    wmma::fragment<wmma::accumulator,16,16,16,float> oacc[3];
    #pragma unroll
    for (int j = 0; j < 3; j++) wmma::fill_fragment(oacc[j], 0.0f);

    // prefetch key-tile 0 (K: 320 chunks, V: 320 chunks)
    #pragma unroll
    for (int l = 0; l < 3; l++) {
        int idx = tid + l*256;
        if (idx < 640) {
            int ch = (idx < 320) ? idx : idx - 320;
            int r = ch/5, c8 = (ch - r*5)*8;
            const bf16* src = ((idx < 320) ? K : V) + base + (size_t)r*DIM + c8;
            bf16* dst = ((idx < 320) ? Ks0 : Vs0) + r*48 + c8;
            __pipeline_memcpy_async(dst, src, 16);
        }
    }
    __pipeline_commit();

    const int NT = LQ/64;   // 32
    for (int it = 0; it < NT; it++) {
        const int cur = it & 1;
        if (it + 1 < NT) {
            const int kt = (it+1)*64;
            bf16* Kd = Ks0 + (cur^1)*3072;
            bf16* Vd = Vs0 + (cur^1)*3072;
            #pragma unroll
            for (int l = 0; l < 3; l++) {
                int idx = tid + l*256;
                if (idx < 640) {
                    int ch = (idx < 320) ? idx : idx - 320;
                    int r = ch/5, c8 = (ch - r*5)*8;
                    const bf16* src = ((idx < 320) ? K : V) + base + (size_t)(kt+r)*DIM + c8;
                    bf16* dst = ((idx < 320) ? Kd : Vd) + r*48 + c8;
                    __pipeline_memcpy_async(dst, src, 16);
                }
            }
            __pipeline_commit();
            __pipeline_wait_prior(1);
        } else {
            __pipeline_wait_prior(0);
        }
        __syncthreads();
        const bf16* Kd = Ks0 + cur*3072;
        const bf16* Vd = Vs0 + cur*3072;

        // S[128,64] = Qs @ Kd^T; warps 4m x 2n, warp tile 32x32, 3 k-steps
        {
            const int wm = wid & 3, wn = wid >> 2;
            wmma::fragment<wmma::accumulator,16,16,16,float> sacc[2][2];
            #pragma unroll
            for (int i = 0; i < 2; i++)
                #pragma unroll
                for (int j = 0; j < 2; j++) wmma::fill_fragment(sacc[i][j], 0.0f);
            #pragma unroll
            for (int kk = 0; kk < 3; kk++) {
                wmma::fragment<wmma::matrix_a,16,16,16,bf16,wmma::row_major> af[2];
                wmma::fragment<wmma::matrix_b,16,16,16,bf16,wmma::col_major> bf[2];
                #pragma unroll
                for (int i = 0; i < 2; i++)
                    wmma::load_matrix_sync(af[i], &Qs[(wm*32 + i*16)*48 + kk*16], 48);
                #pragma unroll
                for (int j = 0; j < 2; j++)
                    wmma::load_matrix_sync(bf[j], &Kd[(wn*32 + j*16)*48 + kk*16], 48);
                #pragma unroll
                for (int i = 0; i < 2; i++)
                    #pragma unroll
                    for (int j = 0; j < 2; j++)
                        wmma::mma_sync(sacc[i][j], af[i], bf[j], sacc[i][j]);
            }
            #pragma unroll
            for (int i = 0; i < 2; i++)
                #pragma unroll
                for (int j = 0; j < 2; j++)
                    wmma::store_matrix_sync(&Ss[(wm*32 + i*16)*72 + wn*32 + j*16],
                                            sacc[i][j], 72, wmma::mem_row_major);
        }
        __syncthreads();

        // P = exp(scale*S) -> bf16; fp32 row sums
        {
            int r = tid >> 1, c0 = (tid & 1) * 32;
            float ps = 0.f;
            #pragma unroll
            for (int c = 0; c < 32; c++) {
                float p = __expf(Ss[r*72 + c0 + c] * scale);
                Ps[r*72 + c0 + c] = __float2bfloat16(p);
                ps += p;
            }
            float other = __shfl_xor_sync(0xffffffff, ps, 1);
            if (!(tid & 1)) lsum[r] += ps + other;
        }
        __syncthreads();

        // O[16,48] += P[16,64] @ V[64,48] per warp (rows wid*16)
        #pragma unroll
        for (int kk = 0; kk < 4; kk++) {
            wmma::fragment<wmma::matrix_a,16,16,16,bf16,wmma::row_major> af;
            wmma::load_matrix_sync(af, &Ps[(wid*16)*72 + kk*16], 72);
            #pragma unroll
            for (int j = 0; j < 3; j++) {
                wmma::fragment<wmma::matrix_b,16,16,16,bf16,wmma::row_major> bfv;
                wmma::load_matrix_sync(bfv, &Vd[(kk*16)*48 + j*16], 48);
                wmma::mma_sync(oacc[j], af, bfv, oacc[j]);
            }
        }
        __syncthreads();
    }

    // epilogue: stage O fp32 in Ss as [128][48], normalize, write bf16
    float* Os = Ss;
    #pragma unroll
    for (int j = 0; j < 3; j++)
        wmma::store_matrix_sync(&Os[(wid*16)*48 + j*16], oacc[j], 48, wmma::mem_row_major);
    __syncthreads();
    #pragma unroll
    for (int l = 0; l < 10; l++) {
        int idx = tid + l*256;              // 128 rows x 20 bf162 pairs
        int r = idx/20, c2 = (idx - r*20)*2;
        float inv = 1.0f / lsum[r];
        __nv_bfloat162 p;
        p.x = __float2bfloat16(Os[r*48 + c2]     * inv);
        p.y = __float2bfloat16(Os[r*48 + c2 + 1] * inv);
        *(__nv_bfloat162*)(O + base + (size_t)(q0+r)*DIM + c2) = p;
    }
}

// ---------------------------------------------------------------------------
extern "C" void kernel_launch(void* const* d_in, const int* in_sizes, int n_in,
                              void* d_out, int out_size) {
    (void)in_sizes; (void)n_in; (void)out_size;
    const float* x    = (const float*)d_in[0];
    const float* ln1g = (const float*)d_in[2];
    const float* ln1b = (const float*)d_in[3];
    const float* wq1  = (const float*)d_in[4];
    const float* wk1  = (const float*)d_in[5];
    const float* wv1  = (const float*)d_in[6];
    const float* wo1  = (const float*)d_in[7];
    const float* bo1  = (const float*)d_in[8];
    const float* ln2g = (const float*)d_in[9];
    const float* ln2b = (const float*)d_in[10];
    const float* wvh  = (const float*)d_in[13];
    const float* wo2  = (const float*)d_in[14];
    const float* bo2  = (const float*)d_in[15];
    const float* ln3g = (const float*)d_in[16];
    const float* ln3b = (const float*)d_in[17];
    const float* wff1 = (const float*)d_in[18];
    const float* bff1 = (const float*)d_in[19];
    const float* wff2 = (const float*)d_in[20];
    const float* bff2 = (const float*)d_in[21];
    float* out = (float*)d_out;

    bf16 *p_h, *p_q, *p_k, *p_v, *p_at, *p_wc, *p_mid, *p_wb;
    float *p_x1, *p_x2;
    cudaGetSymbolAddress((void**)&p_h,   g_h);
    cudaGetSymbolAddress((void**)&p_q,   g_q);
    cudaGetSymbolAddress((void**)&p_k,   g_k);
    cudaGetSymbolAddress((void**)&p_v,   g_v);
    cudaGetSymbolAddress((void**)&p_at,  g_at);
    cudaGetSymbolAddress((void**)&p_x1,  g_x1);
    cudaGetSymbolAddress((void**)&p_x2,  g_x2);
    cudaGetSymbolAddress((void**)&p_wc,  g_wc);
    cudaGetSymbolAddress((void**)&p_mid, g_mid);
    cudaGetSymbolAddress((void**)&p_wb,  g_wb);

    const int gemm_smem  = 128*64*4;                                   // 32768
    const int ff1_smem   = 2*128*64*4;                                 // 65536
    const int flash_smem = (128*48 + 4*64*48)*2 + 128*72*4 + 128*72*2 + 128*4;  // 92672

    static bool attr_set = false;
    if (!attr_set) {
        cudaFuncSetAttribute(gemm_tc<true,true>, cudaFuncAttributeMaxDynamicSharedMemorySize, gemm_smem);
        cudaFuncSetAttribute(qkv_tc,             cudaFuncAttributeMaxDynamicSharedMemorySize, gemm_smem);
        cudaFuncSetAttribute(ff1_geglu,          cudaFuncAttributeMaxDynamicSharedMemorySize, ff1_smem);
        cudaFuncSetAttribute(flash_tc,           cudaFuncAttributeMaxDynamicSharedMemorySize, flash_smem);
        attr_set = true;
    }

    const dim3 gTok(DIM/64, M_TOK/128);       // (5, 32)

    // weight conversion + wc (independent of activations)
    convert_w<<<(WB_TOT + 255)/256, 256>>>(wq1, wk1, wv1, wo1, wff1, wff2, p_wb);
    gemm_f32<<<dim3(5,5), 256>>>(wvh, wo2, p_wc, DIM, DIM, DIM);

    // ---- block 1: self-attention ----
    ln_kernel<<<M_TOK, DIM>>>(x, ln1g, ln1b, p_h);
    qkv_tc<<<dim3(15, M_TOK/128), 256, gemm_smem>>>(p_h, p_wb, p_q, p_k, p_v);
    flash_tc<<<dim3(LQ/128, BATCH*NH), 256, flash_smem>>>(p_q, p_k, p_v, p_at);
    gemm_tc<true,true><<<gTok, 256, gemm_smem>>>(p_at, p_wb + WB_O, bo1, x, p_x1, DIM, DIM);

    // ---- block 2: cross-attn collapses to x2 = x1 + LN(x1) @ (wvh@wo2) + bo2
    ln_kernel<<<M_TOK, DIM>>>(p_x1, ln2g, ln2b, p_h);
    gemm_tc<true,true><<<gTok, 256, gemm_smem>>>(p_h, p_wc, bo2, p_x1, p_x2, DIM, DIM);

    // ---- block 3: GEGLU FF ----
    ln_kernel<<<M_TOK, DIM>>>(p_x2, ln3g, ln3b, p_h);
    ff1_geglu<<<dim3(FF/64, M_TOK/128), 256, ff1_smem>>>(p_h, p_wb + WB_FF1, bff1, p_mid);
    gemm_tc<true,true><<<gTok, 256, gemm_smem>>>(p_mid, p_wb + WB_FF2, bff2, p_x2, out, DIM, FF);
}

// round 13
// speedup vs baseline: 3.3631x; 1.3497x over previous
#include <cuda_runtime.h>
#include <cuda_pipeline.h>
#include <cuda_bf16.h>
#include <mma.h>
#include <math.h>
#include <stddef.h>

using namespace nvcuda;
typedef __nv_bfloat16 bf16;

#define LQ    2048
#define BATCH 2
#define DIM   320
#define NH    8
#define HD    40
#define FF    1280
#define M_TOK (BATCH*LQ)   /* 4096 */

#define GT 4608   /* 64x72 bf16 tile stage (A or B) */

// -------------------- scratch (device globals) -----------------------------
__device__ bf16  g_h  [M_TOK*DIM];
__device__ bf16  g_q  [M_TOK*DIM];
__device__ bf16  g_k  [M_TOK*DIM];
__device__ bf16  g_v  [M_TOK*DIM];
__device__ bf16  g_at [M_TOK*DIM];
__device__ float g_x1 [M_TOK*DIM];
__device__ float g_x2 [M_TOK*DIM];
__device__ bf16  g_wc [DIM*DIM];
__device__ bf16  g_mid[M_TOK*FF];
__device__ bf16  g_wb [4*DIM*DIM + DIM*2*FF + FF*DIM];   // converted weights

#define WB_Q   0
#define WB_K   (DIM*DIM)
#define WB_V   (2*DIM*DIM)
#define WB_O   (3*DIM*DIM)
#define WB_FF1 (4*DIM*DIM)
#define WB_FF2 (4*DIM*DIM + DIM*2*FF)
#define WB_TOT (4*DIM*DIM + DIM*2*FF + FF*DIM)   // 1,638,400

// -------------------- weight fp32 -> bf16 conversion -----------------------
__global__ void convert_w(const float* __restrict__ wq, const float* __restrict__ wk,
                          const float* __restrict__ wv, const float* __restrict__ wo,
                          const float* __restrict__ wf1, const float* __restrict__ wf2,
                          bf16* __restrict__ out) {
    int idx = blockIdx.x * 256 + threadIdx.x;
    if (idx >= WB_TOT) return;
    float v;
    if (idx < WB_FF1) {
        int w = idx / (DIM*DIM), r = idx % (DIM*DIM);
        const float* src = (w == 0) ? wq : (w == 1) ? wk : (w == 2) ? wv : wo;
        v = src[r];
    } else if (idx < WB_FF2) {
        v = wf1[idx - WB_FF1];
    } else {
        v = wf2[idx - WB_FF2];
    }
    out[idx] = __float2bfloat16(v);
}

// -------------------- LayerNorm (fp32 in -> bf16 out) ----------------------
__global__ void ln_kernel(const float* __restrict__ x, const float* __restrict__ g,
                          const float* __restrict__ b, bf16* __restrict__ out) {
    int row = blockIdx.x;
    int t   = threadIdx.x;           // 0..319
    float v = x[(size_t)row*DIM + t];
    float s = v, sq = v*v;
    #pragma unroll
    for (int o = 16; o > 0; o >>= 1) {
        s  += __shfl_xor_sync(0xffffffff, s,  o);
        sq += __shfl_xor_sync(0xffffffff, sq, o);
    }
    __shared__ float ws[10], wq[10];
    __shared__ float mean_s, rstd_s;
    int w = t >> 5;
    if ((t & 31) == 0) { ws[w] = s; wq[w] = sq; }
    __syncthreads();
    if (t == 0) {
        float S = 0.f, Q = 0.f;
        #pragma unroll
        for (int i = 0; i < 10; i++) { S += ws[i]; Q += wq[i]; }
        float m   = S * (1.0f/DIM);
        float var = Q * (1.0f/DIM) - m*m;
        mean_s = m;
        rstd_s = rsqrtf(var + 1e-5f);
    }
    __syncthreads();
    out[(size_t)row*DIM + t] = __float2bfloat16((v - mean_s) * rstd_s * g[t] + b[t]);
}

// -------------------- small fp32 GEMM: wc = wvh @ wo2 (bf16 out) -----------
__global__ void __launch_bounds__(256)
gemm_f32(const float* __restrict__ A, const float* __restrict__ B,
         bf16* __restrict__ C, int M, int N, int K) {
    __shared__ float As[32][64];
    __shared__ float Bs[32][64];
    const int tid = threadIdx.x;
    const int bx = blockIdx.x, by = blockIdx.y;
    const int ty = tid >> 4, tx = tid & 15;
    float acc[4][4] = {};
    const float* Ab = A + (size_t)by * 64 * K;
    const float* Bb = B + (size_t)bx * 64;
    for (int k0 = 0; k0 < K; k0 += 32) {
        #pragma unroll
        for (int l = 0; l < 2; l++) {
            int s  = tid + l*256;
            int ar = s >> 3, ac = (s & 7) << 2;
            float4 va = *(const float4*)(Ab + (size_t)ar*K + k0 + ac);
            As[ac+0][ar] = va.x; As[ac+1][ar] = va.y;
            As[ac+2][ar] = va.z; As[ac+3][ar] = va.w;
        }
        #pragma unroll
        for (int l = 0; l < 2; l++) {
            int s  = tid + l*256;
            int br = s >> 4, bc = (s & 15) << 2;
            *(float4*)(&Bs[br][bc]) = *(const float4*)(Bb + (size_t)(k0+br)*N + bc);
        }
        __syncthreads();
        #pragma unroll
        for (int kk = 0; kk < 32; kk++) {
            float4 a4 = *(const float4*)(&As[kk][ty << 2]);
            float4 b4 = *(const float4*)(&Bs[kk][tx << 2]);
            float a[4] = {a4.x, a4.y, a4.z, a4.w};
            float bb[4] = {b4.x, b4.y, b4.z, b4.w};
            #pragma unroll
            for (int i = 0; i < 4; i++)
                #pragma unroll
                for (int j = 0; j < 4; j++)
                    acc[i][j] += a[i] * bb[j];
        }
        __syncthreads();
    }
    #pragma unroll
    for (int i = 0; i < 4; i++) {
        int r = by*64 + ty*4 + i;
        #pragma unroll
        for (int j = 0; j < 4; j++)
            C[(size_t)r*N + bx*64 + tx*4 + j] = __float2bfloat16(acc[i][j]);
    }
}

// ===================== bf16 TC GEMM core ===================================
// BM=64, BN=64, BK=64. 128 threads = 4 warps (2m x 2n), warp tile 32x32.
// wmma 16x16x16 bf16, fp32 accum. Double-buffered cp.async; 16 MMAs per sync.
template<bool BIAS, bool RESID, bool OBF>
__device__ __forceinline__ void gemm_core(
    const bf16* __restrict__ Ab,     // A + by*64*K  (row stride K)
    const bf16* __restrict__ Bb,     // B + col0     (row stride N)
    const float* __restrict__ biasc,
    const float* __restrict__ resb,
    void* __restrict__ Cb,
    int N, int K, char* smemraw)
{
    bf16* As0 = (bf16*)smemraw;          // 2 x GT
    bf16* Bs0 = As0 + 2*GT;              // 2 x GT
    const int tid = threadIdx.x;
    const int wid = tid >> 5, wm = wid & 1, wn = wid >> 1;

    wmma::fragment<wmma::accumulator,16,16,16,float> acc[2][2];
    #pragma unroll
    for (int i = 0; i < 2; i++)
        #pragma unroll
        for (int j = 0; j < 2; j++) wmma::fill_fragment(acc[i][j], 0.0f);

    // prefetch stage 0
    #pragma unroll
    for (int l = 0; l < 4; l++) {
        int idx = tid + l*128;
        int r = idx >> 3, c8 = (idx & 7) << 3;
        __pipeline_memcpy_async(&As0[r*72 + c8], Ab + (size_t)r*K + c8, 16);
        __pipeline_memcpy_async(&Bs0[r*72 + c8], Bb + (size_t)r*N + c8, 16);
    }
    __pipeline_commit();

    const int nk = K >> 6;
    for (int ik = 0; ik < nk; ik++) {
        const int cur = ik & 1;
        if (ik + 1 < nk) {
            const int k0 = (ik + 1) << 6;
            bf16* As = As0 + (cur^1)*GT;
            bf16* Bs = Bs0 + (cur^1)*GT;
            #pragma unroll
            for (int l = 0; l < 4; l++) {
                int idx = tid + l*128;
                int r = idx >> 3, c8 = (idx & 7) << 3;
                __pipeline_memcpy_async(&As[r*72 + c8], Ab + (size_t)r*K + k0 + c8, 16);
                __pipeline_memcpy_async(&Bs[r*72 + c8], Bb + (size_t)(k0+r)*N + c8, 16);
            }
            __pipeline_commit();
            __pipeline_wait_prior(1);
        } else {
            __pipeline_wait_prior(0);
        }
        __syncthreads();
        const bf16* As = As0 + cur*GT;
        const bf16* Bs = Bs0 + cur*GT;
        #pragma unroll
        for (int kk = 0; kk < 4; kk++) {
            wmma::fragment<wmma::matrix_a,16,16,16,bf16,wmma::row_major> af[2];
            wmma::fragment<wmma::matrix_b,16,16,16,bf16,wmma::row_major> bf[2];
            #pragma unroll
            for (int i = 0; i < 2; i++)
                wmma::load_matrix_sync(af[i], &As[(wm*32 + i*16)*72 + kk*16], 72);
            #pragma unroll
            for (int j = 0; j < 2; j++)
                wmma::load_matrix_sync(bf[j], &Bs[(kk*16)*72 + wn*32 + j*16], 72);
            #pragma unroll
            for (int i = 0; i < 2; i++)
                #pragma unroll
                for (int j = 0; j < 2; j++)
                    wmma::mma_sync(acc[i][j], af[i], bf[j], acc[i][j]);
        }
        __syncthreads();
    }

    // epilogue via fp32 smem stage [64][64]
    float* St = (float*)smemraw;
    #pragma unroll
    for (int i = 0; i < 2; i++)
        #pragma unroll
        for (int j = 0; j < 2; j++)
            wmma::store_matrix_sync(&St[(wm*32 + i*16)*64 + wn*32 + j*16],
                                    acc[i][j], 64, wmma::mem_row_major);
    __syncthreads();
    #pragma unroll
    for (int l = 0; l < 8; l++) {
        int idx = tid + l*128;
        int r = idx >> 4, c4 = (idx & 15) << 2;
        float4 v = *(float4*)&St[r*64 + c4];
        if (BIAS) {
            float4 bb = *(const float4*)(biasc + c4);
            v.x += bb.x; v.y += bb.y; v.z += bb.z; v.w += bb.w;
        }
        if (RESID) {
            float4 rr = *(const float4*)(resb + (size_t)r*N + c4);
            v.x += rr.x; v.y += rr.y; v.z += rr.z; v.w += rr.w;
        }
        if (OBF) {
            bf16* Co = (bf16*)Cb + (size_t)r*N + c4;
            __nv_bfloat162 p0; p0.x = __float2bfloat16(v.x); p0.y = __float2bfloat16(v.y);
            __nv_bfloat162 p1; p1.x = __float2bfloat16(v.z); p1.y = __float2bfloat16(v.w);
            *(__nv_bfloat162*)(Co)     = p0;
            *(__nv_bfloat162*)(Co + 2) = p1;
        } else {
            *(float4*)((float*)Cb + (size_t)r*N + c4) = v;
        }
    }
}

template<bool BIAS, bool RESID>
__global__ void __launch_bounds__(128)
gemm_tc(const bf16* __restrict__ A, const bf16* __restrict__ B,
        const float* __restrict__ bias, const float* __restrict__ res,
        float* __restrict__ C, int N, int K) {
    extern __shared__ char smemraw[];
    const int bx = blockIdx.x, by = blockIdx.y;
    gemm_core<BIAS,RESID,false>(A + (size_t)by*64*K, B + bx*64,
                                BIAS ? bias + bx*64 : nullptr,
                                RESID ? res + (size_t)by*64*N + bx*64 : nullptr,
                                C + (size_t)by*64*N + bx*64, N, K, smemraw);
}

// fused QKV (bf16 out): grid.x = 15 (3 weights x 5 col-tiles)
__global__ void __launch_bounds__(128)
qkv_tc(const bf16* __restrict__ A, const bf16* __restrict__ WB,
       bf16* __restrict__ Oq, bf16* __restrict__ Ok, bf16* __restrict__ Ov) {
    extern __shared__ char smemraw[];
    const int bx = blockIdx.x, by = blockIdx.y;
    const int sel = bx / 5, cx = bx % 5;
    const bf16* B = WB + ((sel == 0) ? WB_Q : (sel == 1) ? WB_K : WB_V);
    bf16*       C = (sel == 0) ? Oq : (sel == 1) ? Ok : Ov;
    gemm_core<false,false,true>(A + (size_t)by*64*DIM, B + cx*64, nullptr, nullptr,
                                C + (size_t)by*64*DIM + cx*64, DIM, DIM, smemraw);
}

// ===================== ff1 + GEGLU fused (bf16, BK=64) =====================
__global__ void __launch_bounds__(128)
ff1_geglu(const bf16* __restrict__ A, const bf16* __restrict__ W,
          const float* __restrict__ bias, bf16* __restrict__ Mid) {
    extern __shared__ char smemraw[];
    bf16* As0 = (bf16*)smemraw;             // 2 x GT
    bf16* Bx0 = As0 + 2*GT;                 // 2 x GT
    bf16* Bg0 = Bx0 + 2*GT;                 // 2 x GT
    const int bx = blockIdx.x, by = blockIdx.y;
    const int tid = threadIdx.x, wid = tid >> 5, wm = wid & 1, wn = wid >> 1;
    const int NW = 2*FF;
    const bf16* Ab  = A + (size_t)by*64*DIM;
    const bf16* Bxb = W + bx*64;
    const bf16* Bgb = W + FF + bx*64;

    wmma::fragment<wmma::accumulator,16,16,16,float> accx[2][2], accg[2][2];
    #pragma unroll
    for (int i = 0; i < 2; i++)
        #pragma unroll
        for (int j = 0; j < 2; j++) {
            wmma::fill_fragment(accx[i][j], 0.0f);
            wmma::fill_fragment(accg[i][j], 0.0f);
        }

    #pragma unroll
    for (int l = 0; l < 4; l++) {
        int idx = tid + l*128;
        int r = idx >> 3, c8 = (idx & 7) << 3;
        __pipeline_memcpy_async(&As0[r*72 + c8], Ab + (size_t)r*DIM + c8, 16);
        __pipeline_memcpy_async(&Bx0[r*72 + c8], Bxb + (size_t)r*NW + c8, 16);
        __pipeline_memcpy_async(&Bg0[r*72 + c8], Bgb + (size_t)r*NW + c8, 16);
    }
    __pipeline_commit();

    const int nk = DIM >> 6;   // 5
    for (int ik = 0; ik < nk; ik++) {
        const int cur = ik & 1;
        if (ik + 1 < nk) {
            const int k0 = (ik + 1) << 6;
            bf16* As = As0 + (cur^1)*GT;
            bf16* Bx = Bx0 + (cur^1)*GT;
            bf16* Bg = Bg0 + (cur^1)*GT;
            #pragma unroll
            for (int l = 0; l < 4; l++) {
                int idx = tid + l*128;
                int r = idx >> 3, c8 = (idx & 7) << 3;
                __pipeline_memcpy_async(&As[r*72 + c8], Ab + (size_t)r*DIM + k0 + c8, 16);
                __pipeline_memcpy_async(&Bx[r*72 + c8], Bxb + (size_t)(k0+r)*NW + c8, 16);
                __pipeline_memcpy_async(&Bg[r*72 + c8], Bgb + (size_t)(k0+r)*NW + c8, 16);
            }
            __pipeline_commit();
            __pipeline_wait_prior(1);
        } else {
            __pipeline_wait_prior(0);
        }
        __syncthreads();
        const bf16* As = As0 + cur*GT;
        const bf16* Bx = Bx0 + cur*GT;
        const bf16* Bg = Bg0 + cur*GT;
        #pragma unroll
        for (int kk = 0; kk < 4; kk++) {
            wmma::fragment<wmma::matrix_a,16,16,16,bf16,wmma::row_major> af[2];
            wmma::fragment<wmma::matrix_b,16,16,16,bf16,wmma::row_major> bfx[2], bfg[2];
            #pragma unroll
            for (int i = 0; i < 2; i++)
                wmma::load_matrix_sync(af[i], &As[(wm*32 + i*16)*72 + kk*16], 72);
            #pragma unroll
            for (int j = 0; j < 2; j++) {
                wmma::load_matrix_sync(bfx[j], &Bx[(kk*16)*72 + wn*32 + j*16], 72);
                wmma::load_matrix_sync(bfg[j], &Bg[(kk*16)*72 + wn*32 + j*16], 72);
            }
            #pragma unroll
            for (int i = 0; i < 2; i++)
                #pragma unroll
                for (int j = 0; j < 2; j++) {
                    wmma::mma_sync(accx[i][j], af[i], bfx[j], accx[i][j]);
                    wmma::mma_sync(accg[i][j], af[i], bfg[j], accg[i][j]);
                }
        }
        __syncthreads();
    }

    float* Stx = (float*)smemraw;          // [64][64]
    float* Stg = Stx + 4096;               // [64][64]
    #pragma unroll
    for (int i = 0; i < 2; i++)
        #pragma unroll
        for (int j = 0; j < 2; j++) {
            wmma::store_matrix_sync(&Stx[(wm*32 + i*16)*64 + wn*32 + j*16], accx[i][j], 64, wmma::mem_row_major);
            wmma::store_matrix_sync(&Stg[(wm*32 + i*16)*64 + wn*32 + j*16], accg[i][j], 64, wmma::mem_row_major);
        }
    __syncthreads();
    #pragma unroll
    for (int l = 0; l < 8; l++) {
        int idx = tid + l*128;
        int r = idx >> 4, c4 = (idx & 15) << 2;
        float4 xv = *(float4*)&Stx[r*64 + c4];
        float4 gv = *(float4*)&Stg[r*64 + c4];
        float4 bxv = *(const float4*)(bias + bx*64 + c4);
        float4 bgv = *(const float4*)(bias + FF + bx*64 + c4);
        float xa[4] = {xv.x+bxv.x, xv.y+bxv.y, xv.z+bxv.z, xv.w+bxv.w};
        float ga[4] = {gv.x+bgv.x, gv.y+bgv.y, gv.z+bgv.z, gv.w+bgv.w};
        bf16 ov[4];
        #pragma unroll
        for (int e = 0; e < 4; e++) {
            float g = ga[e];
            ov[e] = __float2bfloat16(xa[e] * (0.5f * g * (1.f + erff(g * 0.70710678118654752f))));
        }
        bf16* Mo = Mid + (size_t)(by*64 + r)*FF + bx*64 + c4;
        __nv_bfloat162 p0; p0.x = ov[0]; p0.y = ov[1];
        __nv_bfloat162 p1; p1.x = ov[2]; p1.y = ov[3];
        *(__nv_bfloat162*)(Mo)     = p0;
        *(__nv_bfloat162*)(Mo + 2) = p1;
    }
}

// ===================== bf16 tensor-core flash attention ====================
// 128-query tile, 256 threads = 8 warps. Two barriers per key-tile:
//   sync1 (K/V + Ss buffer handoff), S mma 4m x 2n -> fp32 Ss, sync2,
//   consumer warp w exps ITS rows in-place (fp32 -> bf16 overlay), P@V.
// Row sums come free via ones-column in V (col 40 = 1.0 -> O col 40 = l).
__global__ void __launch_bounds__(256)
flash_tc(const bf16* __restrict__ Q, const bf16* __restrict__ K,
         const bf16* __restrict__ V, bf16* __restrict__ O) {
    extern __shared__ char smc[];
    bf16*  Qs  = (bf16*)smc;               // [128][48]
    bf16*  Ks0 = Qs  + 128*48;             // 2 x [64][48]
    bf16*  Vs0 = Ks0 + 2*64*48;            // 2 x [64][48]
    float* Ss  = (float*)(Vs0 + 2*64*48);  // [128][72] fp32; P overlays as bf16 (stride 144)

    const int tid = threadIdx.x, wid = tid >> 5, lane = tid & 31;
    const int b = blockIdx.y >> 3, h = blockIdx.y & 7;
    const int q0 = blockIdx.x * 128;
    const size_t base = ((size_t)b*LQ)*DIM + h*HD;
    const float scale = 0.158113883008419f;    // 1/sqrt(40)

    if (tid < 128) {
        // pads (cols 40..47): Q zero; K zero; V col40 = 1 (row-sum trick), rest 0.
        uint4 z = {0u,0u,0u,0u};
        *(uint4*)&Qs [tid*48 + 40] = z;
        *(uint4*)&Ks0[tid*48 + 40] = z;      // 128 rows = both K stages
        *(uint4*)&Vs0[tid*48 + 40] = z;
        Vs0[tid*48 + 40] = __float2bfloat16(1.0f);
    }
    // Q load (raw bf16; scale folded into exp)
    #pragma unroll
    for (int l = 0; l < 3; l++) {
        int idx = tid + l*256;
        if (idx < 640) {
            int r = idx/5, c8 = (idx - r*5)*8;
            *(uint4*)&Qs[r*48 + c8] = *(const uint4*)(Q + base + (size_t)(q0+r)*DIM + c8);
        }
    }

    wmma::fragment<wmma::accumulator,16,16,16,float> oacc[3];
    #pragma unroll
    for (int j = 0; j < 3; j++) wmma::fill_fragment(oacc[j], 0.0f);

    // prefetch key-tile 0
    #pragma unroll
    for (int l = 0; l < 3; l++) {
        int idx = tid + l*256;
        if (idx < 640) {
            int ch = (idx < 320) ? idx : idx - 320;
            int r = ch/5, c8 = (ch - r*5)*8;
            const bf16* src = ((idx < 320) ? K : V) + base + (size_t)r*DIM + c8;
            bf16* dst = ((idx < 320) ? Ks0 : Vs0) + r*48 + c8;
            __pipeline_memcpy_async(dst, src, 16);
        }
    }
    __pipeline_commit();

    const int NT = LQ/64;   // 32
    for (int it = 0; it < NT; it++) {
        const int cur = it & 1;
        if (it + 1 < NT) {
            const int kt = (it+1)*64;
            bf16* Kd = Ks0 + (cur^1)*3072;
            bf16* Vd = Vs0 + (cur^1)*3072;
            #pragma unroll
            for (int l = 0; l < 3; l++) {
                int idx = tid + l*256;
                if (idx < 640) {
                    int ch = (idx < 320) ? idx : idx - 320;
                    int r = ch/5, c8 = (ch - r*5)*8;
                    const bf16* src = ((idx < 320) ? K : V) + base + (size_t)(kt+r)*DIM + c8;
                    bf16* dst = ((idx < 320) ? Kd : Vd) + r*48 + c8;
                    __pipeline_memcpy_async(dst, src, 16);
                }
            }
            __pipeline_commit();
            __pipeline_wait_prior(1);
        } else {
            __pipeline_wait_prior(0);
        }
        __syncthreads();                               // sync1
        const bf16* Kd = Ks0 + cur*3072;
        const bf16* Vd = Vs0 + cur*3072;

        // S[128,64] = Qs @ Kd^T; warps 4m x 2n, warp tile 32x32, 3 k-steps
        {
            const int wm = wid & 3, wn = wid >> 2;
            wmma::fragment<wmma::accumulator,16,16,16,float> sacc[2][2];
            #pragma unroll
            for (int i = 0; i < 2; i++)
                #pragma unroll
                for (int j = 0; j < 2; j++) wmma::fill_fragment(sacc[i][j], 0.0f);
            #pragma unroll
            for (int kk = 0; kk < 3; kk++) {
                wmma::fragment<wmma::matrix_a,16,16,16,bf16,wmma::row_major> af[2];
                wmma::fragment<wmma::matrix_b,16,16,16,bf16,wmma::col_major> bf[2];
                #pragma unroll
                for (int i = 0; i < 2; i++)
                    wmma::load_matrix_sync(af[i], &Qs[(wm*32 + i*16)*48 + kk*16], 48);
                #pragma unroll
                for (int j = 0; j < 2; j++)
                    wmma::load_matrix_sync(bf[j], &Kd[(wn*32 + j*16)*48 + kk*16], 48);
                #pragma unroll
                for (int i = 0; i < 2; i++)
                    #pragma unroll
                    for (int j = 0; j < 2; j++)
                        wmma::mma_sync(sacc[i][j], af[i], bf[j], sacc[i][j]);
            }
            #pragma unroll
            for (int i = 0; i < 2; i++)
                #pragma unroll
                for (int j = 0; j < 2; j++)
                    wmma::store_matrix_sync(&Ss[(wm*32 + i*16)*72 + wn*32 + j*16],
                                            sacc[i][j], 72, wmma::mem_row_major);
        }
        __syncthreads();                               // sync2

        // consumer warp w: exp its 16 rows in-place (fp32 [72] -> bf16 stride 144)
        {
            int r  = wid*16 + (lane >> 1);
            int c0 = (lane & 1) * 32;
            const float* srow = &Ss[r*72 + c0];
            float vals[32];
            #pragma unroll
            for (int c = 0; c < 32; c++) vals[c] = __expf(srow[c] * scale);
            __syncwarp();
            bf16* prow = (bf16*)&Ss[r*72];
            #pragma unroll
            for (int c = 0; c < 16; c++) {
                __nv_bfloat162 p;
                p.x = __float2bfloat16(vals[2*c]);
                p.y = __float2bfloat16(vals[2*c+1]);
                *(__nv_bfloat162*)(prow + c0 + 2*c) = p;
            }
            __syncwarp();
        }

        // O[16,48] += P[16,64] @ V[64,48] per warp (rows wid*16); P stride 144
        const bf16* Pw = (const bf16*)Ss;
        #pragma unroll
        for (int kk = 0; kk < 4; kk++) {
            wmma::fragment<wmma::matrix_a,16,16,16,bf16,wmma::row_major> af;
            wmma::load_matrix_sync(af, &Pw[(wid*16)*144 + kk*16], 144);
            #pragma unroll
            for (int j = 0; j < 3; j++) {
                wmma::fragment<wmma::matrix_b,16,16,16,bf16,wmma::row_major> bfv;
                wmma::load_matrix_sync(bfv, &Vd[(kk*16)*48 + j*16], 48);
                wmma::mma_sync(oacc[j], af, bfv, oacc[j]);
            }
        }
    }

    // epilogue: per-warp [16][48] fp32 stage in Ss, normalize by col 40
    __syncthreads();
    float* Ow = (float*)Ss + wid*16*48;
    #pragma unroll
    for (int j = 0; j < 3; j++)
        wmma::store_matrix_sync(&Ow[j*16], oacc[j], 48, wmma::mem_row_major);
    __syncwarp();
    #pragma unroll
    for (int l = 0; l < 5; l++) {
        int idx = lane + l*32;              // 16 rows x 10 f4 = 160
        int r = idx/10, c4 = (idx - r*10)*4;
        float inv = 1.0f / Ow[r*48 + 40];
        float4 v = *(float4*)&Ow[r*48 + c4];
        __nv_bfloat162 p0; p0.x = __float2bfloat16(v.x*inv); p0.y = __float2bfloat16(v.y*inv);
        __nv_bfloat162 p1; p1.x = __float2bfloat16(v.z*inv); p1.y = __float2bfloat16(v.w*inv);
        bf16* dst = O + base + (size_t)(q0 + wid*16 + r)*DIM + c4;
        *(__nv_bfloat162*)(dst)     = p0;
        *(__nv_bfloat162*)(dst + 2) = p1;
    }
}

// ---------------------------------------------------------------------------
extern "C" void kernel_launch(void* const* d_in, const int* in_sizes, int n_in,
                              void* d_out, int out_size) {
    (void)in_sizes; (void)n_in; (void)out_size;
    const float* x    = (const float*)d_in[0];
    const float* ln1g = (const float*)d_in[2];
    const float* ln1b = (const float*)d_in[3];
    const float* wq1  = (const float*)d_in[4];
    const float* wk1  = (const float*)d_in[5];
    const float* wv1  = (const float*)d_in[6];
    const float* wo1  = (const float*)d_in[7];
    const float* bo1  = (const float*)d_in[8];
    const float* ln2g = (const float*)d_in[9];
    const float* ln2b = (const float*)d_in[10];
    const float* wvh  = (const float*)d_in[13];
    const float* wo2  = (const float*)d_in[14];
    const float* bo2  = (const float*)d_in[15];
    const float* ln3g = (const float*)d_in[16];
    const float* ln3b = (const float*)d_in[17];
    const float* wff1 = (const float*)d_in[18];
    const float* bff1 = (const float*)d_in[19];
    const float* wff2 = (const float*)d_in[20];
    const float* bff2 = (const float*)d_in[21];
    float* out = (float*)d_out;

    bf16 *p_h, *p_q, *p_k, *p_v, *p_at, *p_wc, *p_mid, *p_wb;
    float *p_x1, *p_x2;
    cudaGetSymbolAddress((void**)&p_h,   g_h);
    cudaGetSymbolAddress((void**)&p_q,   g_q);
    cudaGetSymbolAddress((void**)&p_k,   g_k);
    cudaGetSymbolAddress((void**)&p_v,   g_v);
    cudaGetSymbolAddress((void**)&p_at,  g_at);
    cudaGetSymbolAddress((void**)&p_x1,  g_x1);
    cudaGetSymbolAddress((void**)&p_x2,  g_x2);
    cudaGetSymbolAddress((void**)&p_wc,  g_wc);
    cudaGetSymbolAddress((void**)&p_mid, g_mid);
    cudaGetSymbolAddress((void**)&p_wb,  g_wb);

    const int gemm_smem  = 4*GT*2;                           // 36864
    const int ff1_smem   = 6*GT*2;                           // 55296
    const int flash_smem = (128*48 + 4*64*48)*2 + 128*72*4;  // 73728

    static bool attr_set = false;
    if (!attr_set) {
        cudaFuncSetAttribute(ff1_geglu, cudaFuncAttributeMaxDynamicSharedMemorySize, ff1_smem);
        cudaFuncSetAttribute(flash_tc,  cudaFuncAttributeMaxDynamicSharedMemorySize, flash_smem);
        attr_set = true;
    }

    const dim3 gTok(DIM/64, M_TOK/64);        // (5, 64) = 320 blocks

    // weight conversion + wc (independent of activations)
    convert_w<<<(WB_TOT + 255)/256, 256>>>(wq1, wk1, wv1, wo1, wff1, wff2, p_wb);
    gemm_f32<<<dim3(5,5), 256>>>(wvh, wo2, p_wc, DIM, DIM, DIM);

    // ---- block 1: self-attention ----
    ln_kernel<<<M_TOK, DIM>>>(x, ln1g, ln1b, p_h);
    qkv_tc<<<dim3(15, M_TOK/64), 128, gemm_smem>>>(p_h, p_wb, p_q, p_k, p_v);
    flash_tc<<<dim3(LQ/128, BATCH*NH), 256, flash_smem>>>(p_q, p_k, p_v, p_at);
    gemm_tc<true,true><<<gTok, 128, gemm_smem>>>(p_at, p_wb + WB_O, bo1, x, p_x1, DIM, DIM);

    // ---- block 2: cross-attn collapses to x2 = x1 + LN(x1) @ (wvh@wo2) + bo2
    ln_kernel<<<M_TOK, DIM>>>(p_x1, ln2g, ln2b, p_h);
    gemm_tc<true,true><<<gTok, 128, gemm_smem>>>(p_h, p_wc, bo2, p_x1, p_x2, DIM, DIM);

    // ---- block 3: GEGLU FF ----
    ln_kernel<<<M_TOK, DIM>>>(p_x2, ln3g, ln3b, p_h);
    ff1_geglu<<<dim3(FF/64, M_TOK/64), 128, ff1_smem>>>(p_h, p_wb + WB_FF1, bff1, p_mid);
    gemm_tc<true,true><<<gTok, 128, gemm_smem>>>(p_mid, p_wb + WB_FF2, bff2, p_x2, out, DIM, FF);
}